// round 12
// baseline (speedup 1.0000x reference)
#include <cuda_runtime.h>
#include <cuda_fp16.h>
#include <cstdint>

#define NN 100000
#define EE 1600000
#define FIN 128
#define HID 64
#define NCLS 16

#define DSTRIDE 64          // fixed CSR row stride (max degree ~45 << 64)

// ---- scratch (__device__ globals: allocation-free rule) ----
__device__ __align__(16) int    g_cnt[NN];                     // degree (hist)
__device__ __align__(16) int    g_cursor[NN];                  // fill cursor
__device__ __align__(16) int2   g_csr[(size_t)NN * DSTRIDE];   // {src, w_bits}
__device__ __align__(16) __half g_h16[(size_t)NN * HID];       // ping (L1 in, L3 in)
__device__ __align__(16) __half g_h16b[(size_t)NN * HID];      // pong (L2 in)

static inline int cdiv(long long a, int b) { return (int)((a + b - 1) / b); }

// ---- side stream + events for capture fork/join (static init, no dev mem) ----
struct HxAsync {
    cudaStream_t s1;
    cudaEvent_t e_fork, e_join;
    HxAsync() {
        cudaStreamCreateWithFlags(&s1, cudaStreamNonBlocking);
        cudaEventCreateWithFlags(&e_fork, cudaEventDisableTiming);
        cudaEventCreateWithFlags(&e_join, cudaEventDisableTiming);
    }
};
static HxAsync g_hx;

// ---------------------------------------------------------------------------
// CSR build (scan-free, dinv-free)
// ---------------------------------------------------------------------------
__global__ void k_zero() {
    int i = blockIdx.x * blockDim.x + threadIdx.x;
    if (i < NN) {
        g_cnt[i] = 0;
        g_cursor[i] = 0;
    }
}

__global__ void k_hist(const int* __restrict__ ei) {
    int t = blockIdx.x * blockDim.x + threadIdx.x;
    if (t >= EE / 4) return;
    int4 d = *reinterpret_cast<const int4*>(ei + EE + 4 * t);
    atomicAdd(&g_cnt[d.x], 1);
    atomicAdd(&g_cnt[d.y], 1);
    atomicAdd(&g_cnt[d.z], 1);
    atomicAdd(&g_cnt[d.w], 1);
}

__global__ void k_fill(const int* __restrict__ ei) {
    int e = blockIdx.x * blockDim.x + threadIdx.x;
    if (e >= EE) return;
    int s = ei[e];
    int d = ei[EE + e];
    float w = rsqrtf(1.0f + (float)__ldg(&g_cnt[s])) *
              rsqrtf(1.0f + (float)__ldg(&g_cnt[d]));
    int slot = atomicAdd(&g_cursor[d], 1);
    if (slot > DSTRIDE - 1) slot = DSTRIDE - 1;   // OOB guard (never triggers)
    g_csr[(size_t)d * DSTRIDE + slot] = make_int2(s, __float_as_int(w));
}

// ---------------------------------------------------------------------------
// GEMM (layer 1 only): g_h16 = fp16(X @ W1). One thread per node. (R5 form)
// ---------------------------------------------------------------------------
template <int K, int O>
__global__ void k_gemm(const float* __restrict__ X, const float* __restrict__ W) {
    __shared__ __align__(16) float Ws[K * O];
    for (int i = threadIdx.x; i < K * O; i += blockDim.x) Ws[i] = W[i];
    __syncthreads();

    int node = blockIdx.x * blockDim.x + threadIdx.x;
    if (node >= NN) return;

    float4 acc[O / 4];
#pragma unroll
    for (int o = 0; o < O / 4; ++o) acc[o] = make_float4(0.f, 0.f, 0.f, 0.f);

    const float4* xr = reinterpret_cast<const float4*>(X + (size_t)node * K);
    for (int k4 = 0; k4 < K / 4; ++k4) {
        float4 xv = xr[k4];
        float xk[4] = {xv.x, xv.y, xv.z, xv.w};
#pragma unroll
        for (int kk = 0; kk < 4; ++kk) {
            const float4* wr = reinterpret_cast<const float4*>(&Ws[(k4 * 4 + kk) * O]);
#pragma unroll
            for (int o = 0; o < O / 4; ++o) {
                float4 w = wr[o];
                acc[o].x = fmaf(xk[kk], w.x, acc[o].x);
                acc[o].y = fmaf(xk[kk], w.y, acc[o].y);
                acc[o].z = fmaf(xk[kk], w.z, acc[o].z);
                acc[o].w = fmaf(xk[kk], w.w, acc[o].w);
            }
        }
    }

    __align__(16) __half2 hbuf[O / 2];
#pragma unroll
    for (int o = 0; o < O / 4; ++o) {
        hbuf[2 * o]     = __floats2half2_rn(acc[o].x, acc[o].y);
        hbuf[2 * o + 1] = __floats2half2_rn(acc[o].z, acc[o].w);
    }
    uint4* dst = reinterpret_cast<uint4*>(&g_h16[(size_t)node * O]);
    const uint4* srcb = reinterpret_cast<const uint4*>(hbuf);
#pragma unroll
    for (int i = 0; i < (O * 2) / 16; ++i) dst[i] = srcb[i];
}

// ---------------------------------------------------------------------------
// Fused gather + next-layer GEMM. 2 nodes/warp, 16 lanes/node.
// Gather: agg = sum_e h[src]*w + h[node]/(1+deg) + bias, relu.
// Then shuffle-GEMM: the 16-lane group holds the node's 64-vector (4/lane);
// 16 broadcast rounds compute next = row @ W into OUT outputs.
// OUT==64: each lane owns 4 outputs -> fp16 store to hout.
// OUT==16: each lane owns 1 output  -> fp16 store to hout.
// STORE_F32: also write the relu'd gather row (latent) to fout.
// ---------------------------------------------------------------------------
template <int OUT, bool STORE_F32>
__global__ void __launch_bounds__(256, 6)
k_gather_gemm(const __half* __restrict__ hin, const float* __restrict__ b,
              const float* __restrict__ W, __half* __restrict__ hout,
              float* __restrict__ fout) {
    __shared__ __align__(16) float Ws[HID * OUT];
    for (int i = threadIdx.x; i < HID * OUT; i += blockDim.x) Ws[i] = W[i];
    __syncthreads();

    int warp = blockIdx.x * (blockDim.x >> 5) + (threadIdx.x >> 5);
    int half = (threadIdx.x >> 4) & 1;
    int node = warp * 2 + half;          // NN even; grid sized exactly
    int lane = threadIdx.x & 15;

    int cnt = __ldg(&g_cnt[node]);
    size_t beg = (size_t)node * DSTRIDE;
    int ocnt = __shfl_xor_sync(0xffffffffu, cnt, 16);
    int maxcnt = cnt > ocnt ? cnt : ocnt;

    float4 acc = make_float4(0.f, 0.f, 0.f, 0.f);
    int2 c_cur = make_int2(0, 0);
    if (0 < cnt) c_cur = __ldg(&g_csr[beg]);

#pragma unroll 2
    for (int k = 0; k < maxcnt; ++k) {
        int2 c_next = c_cur;
        if (k + 1 < cnt) c_next = __ldg(&g_csr[beg + k + 1]);   // prefetch ahead
        if (k < cnt) {
            float w = __int_as_float(c_cur.y);
            uint2 u = *reinterpret_cast<const uint2*>(&hin[(size_t)c_cur.x * HID + 4 * lane]);
            float2 f01 = __half22float2(*reinterpret_cast<const __half2*>(&u.x));
            float2 f23 = __half22float2(*reinterpret_cast<const __half2*>(&u.y));
            acc.x = fmaf(f01.x, w, acc.x);
            acc.y = fmaf(f01.y, w, acc.y);
            acc.z = fmaf(f23.x, w, acc.z);
            acc.w = fmaf(f23.y, w, acc.w);
        }
        c_cur = c_next;
    }

    // self-loop + bias + relu
    {
        float di = rsqrtf(1.0f + (float)cnt);
        float s2 = di * di;
        uint2 u = *reinterpret_cast<const uint2*>(&hin[(size_t)node * HID + 4 * lane]);
        float2 f01 = __half22float2(*reinterpret_cast<const __half2*>(&u.x));
        float2 f23 = __half22float2(*reinterpret_cast<const __half2*>(&u.y));
        float4 bv = *reinterpret_cast<const float4*>(&b[4 * lane]);
        acc.x = fmaxf(fmaf(f01.x, s2, acc.x) + bv.x, 0.f);
        acc.y = fmaxf(fmaf(f01.y, s2, acc.y) + bv.y, 0.f);
        acc.z = fmaxf(fmaf(f23.x, s2, acc.z) + bv.z, 0.f);
        acc.w = fmaxf(fmaf(f23.y, s2, acc.w) + bv.w, 0.f);
    }

    if (STORE_F32)
        *reinterpret_cast<float4*>(&fout[(size_t)node * HID + 4 * lane]) = acc;

    // ---- shuffle-GEMM: next = row @ W ----
    if (OUT == 64) {
        float4 g = make_float4(0.f, 0.f, 0.f, 0.f);
#pragma unroll
        for (int r = 0; r < 16; ++r) {
            float vx = __shfl_sync(0xffffffffu, acc.x, r, 16);
            float vy = __shfl_sync(0xffffffffu, acc.y, r, 16);
            float vz = __shfl_sync(0xffffffffu, acc.z, r, 16);
            float vw = __shfl_sync(0xffffffffu, acc.w, r, 16);
            const float4* w0 = reinterpret_cast<const float4*>(&Ws[(4 * r + 0) * 64 + 4 * lane]);
            const float4* w1 = reinterpret_cast<const float4*>(&Ws[(4 * r + 1) * 64 + 4 * lane]);
            const float4* w2 = reinterpret_cast<const float4*>(&Ws[(4 * r + 2) * 64 + 4 * lane]);
            const float4* w3 = reinterpret_cast<const float4*>(&Ws[(4 * r + 3) * 64 + 4 * lane]);
            float4 a = *w0, c = *w1, d = *w2, e = *w3;
            g.x = fmaf(vx, a.x, g.x); g.y = fmaf(vx, a.y, g.y);
            g.z = fmaf(vx, a.z, g.z); g.w = fmaf(vx, a.w, g.w);
            g.x = fmaf(vy, c.x, g.x); g.y = fmaf(vy, c.y, g.y);
            g.z = fmaf(vy, c.z, g.z); g.w = fmaf(vy, c.w, g.w);
            g.x = fmaf(vz, d.x, g.x); g.y = fmaf(vz, d.y, g.y);
            g.z = fmaf(vz, d.z, g.z); g.w = fmaf(vz, d.w, g.w);
            g.x = fmaf(vw, e.x, g.x); g.y = fmaf(vw, e.y, g.y);
            g.z = fmaf(vw, e.z, g.z); g.w = fmaf(vw, e.w, g.w);
        }
        __half2 h01 = __floats2half2_rn(g.x, g.y);
        __half2 h23 = __floats2half2_rn(g.z, g.w);
        uint2 pk = make_uint2(*reinterpret_cast<uint32_t*>(&h01),
                              *reinterpret_cast<uint32_t*>(&h23));
        *reinterpret_cast<uint2*>(&hout[(size_t)node * 64 + 4 * lane]) = pk;
    } else {
        float g = 0.f;
#pragma unroll
        for (int r = 0; r < 16; ++r) {
            float vx = __shfl_sync(0xffffffffu, acc.x, r, 16);
            float vy = __shfl_sync(0xffffffffu, acc.y, r, 16);
            float vz = __shfl_sync(0xffffffffu, acc.z, r, 16);
            float vw = __shfl_sync(0xffffffffu, acc.w, r, 16);
            g = fmaf(vx, Ws[(4 * r + 0) * 16 + lane], g);
            g = fmaf(vy, Ws[(4 * r + 1) * 16 + lane], g);
            g = fmaf(vz, Ws[(4 * r + 2) * 16 + lane], g);
            g = fmaf(vw, Ws[(4 * r + 3) * 16 + lane], g);
        }
        hout[(size_t)node * 16 + lane] = __float2half_rn(g);
    }
}

// ---------------------------------------------------------------------------
// Gather (O=16): 2 nodes per warp, 16 lanes x 1 half; final logits layer.
// ---------------------------------------------------------------------------
__global__ void __launch_bounds__(256, 8)
k_gather16(const __half* __restrict__ hin, const float* __restrict__ b,
           float* __restrict__ out) {
    int warp = blockIdx.x * (blockDim.x >> 5) + (threadIdx.x >> 5);
    int half = (threadIdx.x >> 4) & 1;
    int node = warp * 2 + half;
    int lane = threadIdx.x & 15;

    int cnt = __ldg(&g_cnt[node]);
    size_t beg = (size_t)node * DSTRIDE;
    int ocnt = __shfl_xor_sync(0xffffffffu, cnt, 16);
    int maxcnt = cnt > ocnt ? cnt : ocnt;

    float acc = 0.f;
    int2 c_cur = make_int2(0, 0);
    if (0 < cnt) c_cur = __ldg(&g_csr[beg]);

#pragma unroll 2
    for (int k = 0; k < maxcnt; ++k) {
        int2 c_next = c_cur;
        if (k + 1 < cnt) c_next = __ldg(&g_csr[beg + k + 1]);
        if (k < cnt) {
            float w = __int_as_float(c_cur.y);
            float hv = __half2float(hin[(size_t)c_cur.x * NCLS + lane]);
            acc = fmaf(hv, w, acc);
        }
        c_cur = c_next;
    }

    float di = rsqrtf(1.0f + (float)cnt);
    float hv = __half2float(hin[(size_t)node * NCLS + lane]);
    acc = fmaf(hv, di * di, acc) + __ldg(&b[lane]);
    out[(size_t)node * NCLS + lane] = acc;
}

// ---------------------------------------------------------------------------
// Launch: CSR build || layer-1 GEMM; then 3 fused kernels.
// ---------------------------------------------------------------------------
extern "C" void kernel_launch(void* const* d_in, const int* in_sizes, int n_in,
                              void* d_out, int out_size) {
    const float* x  = (const float*)d_in[0];
    const int*   ei = (const int*)  d_in[1];
    const float* W1 = (const float*)d_in[2];
    const float* b1 = (const float*)d_in[3];
    const float* Wh = (const float*)d_in[4];
    const float* bh = (const float*)d_in[5];
    const float* W2 = (const float*)d_in[6];
    const float* b2 = (const float*)d_in[7];

    float* logits = (float*)d_out;                       // [N, 16]
    float* latent = (float*)d_out + (size_t)NN * NCLS;   // [N, 64]

    __half *hA, *hB;
    cudaGetSymbolAddress((void**)&hA, g_h16);
    cudaGetSymbolAddress((void**)&hB, g_h16b);

    const int T = 256;
    const int GB = cdiv(NN, 16);   // 2 nodes/warp, 8 warps/block

    // ---- fork: layer-1 GEMM on side stream ----
    cudaEventRecord(g_hx.e_fork, 0);
    cudaStreamWaitEvent(g_hx.s1, g_hx.e_fork, 0);
    k_gemm<FIN, HID><<<cdiv(NN, 128), 128, 0, g_hx.s1>>>(x, W1);
    cudaEventRecord(g_hx.e_join, g_hx.s1);

    // ---- CSR build on default stream (concurrent with GEMM1) ----
    k_zero<<<cdiv(NN, T), T>>>();
    k_hist<<<cdiv(EE / 4, T), T>>>(ei);
    k_fill<<<cdiv(EE, T), T>>>(ei);

    // ---- join ----
    cudaStreamWaitEvent(0, g_hx.e_join, 0);

    // layer 1 gather + layer 2 GEMM fused:  h16 -> relu(agg)+b1 -> @Wh -> h16b
    k_gather_gemm<HID, false><<<GB, T>>>(hA, b1, Wh, hB, nullptr);

    // layer 2 gather + layer 3 GEMM fused:  h16b -> relu(agg)+bh -> latent, @W2 -> h16
    k_gather_gemm<NCLS, true><<<GB, T>>>(hB, bh, W2, hA, latent);

    // layer 3 gather: logits
    k_gather16<<<GB, T>>>(hA, b2, logits);
}

// round 14
// speedup vs baseline: 1.0444x; 1.0444x over previous
#include <cuda_runtime.h>
#include <cuda_fp16.h>
#include <cstdint>

#define NN 100000
#define EE 1600000
#define FIN 128
#define HID 64
#define NCLS 16

#define DSTRIDE 64          // fixed CSR row stride (max degree ~45 << 64)

// ---- scratch (__device__ globals: allocation-free rule) ----
__device__ __align__(16) int    g_cnt[NN];                    // degree (atomic cursor)
__device__ __align__(16) float  g_dinv[NN];                   // rsqrt(1+deg)
__device__ __align__(16) int    g_csr[(size_t)NN * DSTRIDE];  // src only (4B/edge)
__device__ __align__(16) __half g_h16[(size_t)NN * HID];      // fp16 GEMM output
__device__ __align__(16) float  g_x1[(size_t)NN * HID];       // layer-1 output (fp32)

static inline int cdiv(long long a, int b) { return (int)((a + b - 1) / b); }

// ---- side stream + events for capture fork/join (static init, no dev mem) ----
struct HxAsync {
    cudaStream_t s1;
    cudaEvent_t e_fork, e_join;
    HxAsync() {
        cudaStreamCreateWithFlags(&s1, cudaStreamNonBlocking);
        cudaEventCreateWithFlags(&e_fork, cudaEventDisableTiming);
        cudaEventCreateWithFlags(&e_join, cudaEventDisableTiming);
    }
};
static HxAsync g_hx;

// ---------------------------------------------------------------------------
// CSR build: ONE pass, ONE atomic per edge. cnt[d] is hist AND slot cursor.
// ---------------------------------------------------------------------------
__global__ void k_histfill(const int* __restrict__ ei) {
    int t = blockIdx.x * blockDim.x + threadIdx.x;
    if (t >= EE / 4) return;
    int4 s4 = *reinterpret_cast<const int4*>(ei + 4 * t);
    int4 d4 = *reinterpret_cast<const int4*>(ei + EE + 4 * t);
    int slot;
    slot = atomicAdd(&g_cnt[d4.x], 1); if (slot > DSTRIDE - 1) slot = DSTRIDE - 1;
    g_csr[(size_t)d4.x * DSTRIDE + slot] = s4.x;
    slot = atomicAdd(&g_cnt[d4.y], 1); if (slot > DSTRIDE - 1) slot = DSTRIDE - 1;
    g_csr[(size_t)d4.y * DSTRIDE + slot] = s4.y;
    slot = atomicAdd(&g_cnt[d4.z], 1); if (slot > DSTRIDE - 1) slot = DSTRIDE - 1;
    g_csr[(size_t)d4.z * DSTRIDE + slot] = s4.z;
    slot = atomicAdd(&g_cnt[d4.w], 1); if (slot > DSTRIDE - 1) slot = DSTRIDE - 1;
    g_csr[(size_t)d4.w * DSTRIDE + slot] = s4.w;
}

__global__ void k_dinv() {
    int i = blockIdx.x * blockDim.x + threadIdx.x;
    if (i < NN) g_dinv[i] = rsqrtf(1.0f + (float)g_cnt[i]);
}

// ---------------------------------------------------------------------------
// GEMM: g_h16 = fp16(X @ W). One thread per node; fp32 accumulate. (R5 form)
// ---------------------------------------------------------------------------
template <int K, int O>
__global__ void k_gemm(const float* __restrict__ X, const float* __restrict__ W) {
    __shared__ __align__(16) float Ws[K * O];
    for (int i = threadIdx.x; i < K * O; i += blockDim.x) Ws[i] = W[i];
    __syncthreads();

    int node = blockIdx.x * blockDim.x + threadIdx.x;
    if (node >= NN) return;

    float4 acc[O / 4];
#pragma unroll
    for (int o = 0; o < O / 4; ++o) acc[o] = make_float4(0.f, 0.f, 0.f, 0.f);

    const float4* xr = reinterpret_cast<const float4*>(X + (size_t)node * K);
    for (int k4 = 0; k4 < K / 4; ++k4) {
        float4 xv = xr[k4];
        float xk[4] = {xv.x, xv.y, xv.z, xv.w};
#pragma unroll
        for (int kk = 0; kk < 4; ++kk) {
            const float4* wr = reinterpret_cast<const float4*>(&Ws[(k4 * 4 + kk) * O]);
#pragma unroll
            for (int o = 0; o < O / 4; ++o) {
                float4 w = wr[o];
                acc[o].x = fmaf(xk[kk], w.x, acc[o].x);
                acc[o].y = fmaf(xk[kk], w.y, acc[o].y);
                acc[o].z = fmaf(xk[kk], w.z, acc[o].z);
                acc[o].w = fmaf(xk[kk], w.w, acc[o].w);
            }
        }
    }

    __align__(16) __half2 hbuf[O / 2];
#pragma unroll
    for (int o = 0; o < O / 4; ++o) {
        hbuf[2 * o]     = __floats2half2_rn(acc[o].x, acc[o].y);
        hbuf[2 * o + 1] = __floats2half2_rn(acc[o].z, acc[o].w);
    }
    uint4* dst = reinterpret_cast<uint4*>(&g_h16[(size_t)node * O]);
    const uint4* srcb = reinterpret_cast<const uint4*>(hbuf);
#pragma unroll
    for (int i = 0; i < (O * 2) / 16; ++i) dst[i] = srcb[i];
}

// ---------------------------------------------------------------------------
// Gather (O=64): 2 nodes/warp, 16 lanes/node; joint max-deg loop.
// acc = sum_e h[src]*dinv[src]  (dinv[dst] factored out of the loop):
// out = (acc + h[node]*dinv)*dinv + b, relu. CSR+dinv pipelined 1 ahead.
// ---------------------------------------------------------------------------
template <bool RELU>
__global__ void __launch_bounds__(256, 8)
k_gather64(const float* __restrict__ b, float* __restrict__ out) {
    int warp = blockIdx.x * (blockDim.x >> 5) + (threadIdx.x >> 5);
    int half = (threadIdx.x >> 4) & 1;
    int node = warp * 2 + half;          // NN even; grid sized exactly
    int lane = threadIdx.x & 15;

    int cnt = __ldg(&g_cnt[node]);
    size_t beg = (size_t)node * DSTRIDE;
    int ocnt = __shfl_xor_sync(0xffffffffu, cnt, 16);
    int maxcnt = cnt > ocnt ? cnt : ocnt;

    float4 acc = make_float4(0.f, 0.f, 0.f, 0.f);
    int   s_cur = 0;
    float dv_cur = 0.f;
    if (0 < cnt) {
        s_cur = __ldg(&g_csr[beg]);
        dv_cur = __ldg(&g_dinv[s_cur]);
    }

#pragma unroll 2
    for (int k = 0; k < maxcnt; ++k) {
        int   s_next = s_cur;
        float dv_next = dv_cur;
        if (k + 1 < cnt) {
            s_next = __ldg(&g_csr[beg + k + 1]);     // prefetch ahead
            dv_next = __ldg(&g_dinv[s_next]);
        }
        if (k < cnt) {
            uint2 u = *reinterpret_cast<const uint2*>(&g_h16[(size_t)s_cur * HID + 4 * lane]);
            float2 f01 = __half22float2(*reinterpret_cast<__half2*>(&u.x));
            float2 f23 = __half22float2(*reinterpret_cast<__half2*>(&u.y));
            acc.x = fmaf(f01.x, dv_cur, acc.x);
            acc.y = fmaf(f01.y, dv_cur, acc.y);
            acc.z = fmaf(f23.x, dv_cur, acc.z);
            acc.w = fmaf(f23.y, dv_cur, acc.w);
        }
        s_cur = s_next;
        dv_cur = dv_next;
    }

    float di = rsqrtf(1.0f + (float)cnt);
    uint2 u = *reinterpret_cast<const uint2*>(&g_h16[(size_t)node * HID + 4 * lane]);
    float2 f01 = __half22float2(*reinterpret_cast<__half2*>(&u.x));
    float2 f23 = __half22float2(*reinterpret_cast<__half2*>(&u.y));
    float4 bv = *reinterpret_cast<const float4*>(&b[4 * lane]);
    // (acc + h_node*di)*di + b
    acc.x = fmaf(f01.x, di, acc.x) * di + bv.x;
    acc.y = fmaf(f01.y, di, acc.y) * di + bv.y;
    acc.z = fmaf(f23.x, di, acc.z) * di + bv.z;
    acc.w = fmaf(f23.y, di, acc.w) * di + bv.w;
    if (RELU) {
        acc.x = fmaxf(acc.x, 0.f);
        acc.y = fmaxf(acc.y, 0.f);
        acc.z = fmaxf(acc.z, 0.f);
        acc.w = fmaxf(acc.w, 0.f);
    }
    *reinterpret_cast<float4*>(&out[(size_t)node * HID + 4 * lane]) = acc;
}

// ---------------------------------------------------------------------------
// Gather (O=16): 2 nodes/warp, 16 lanes x 1 half; same factored weights.
// ---------------------------------------------------------------------------
template <bool RELU>
__global__ void __launch_bounds__(256, 8)
k_gather16(const float* __restrict__ b, float* __restrict__ out) {
    int warp = blockIdx.x * (blockDim.x >> 5) + (threadIdx.x >> 5);
    int half = (threadIdx.x >> 4) & 1;
    int node = warp * 2 + half;
    int lane = threadIdx.x & 15;

    int cnt = __ldg(&g_cnt[node]);
    size_t beg = (size_t)node * DSTRIDE;
    int ocnt = __shfl_xor_sync(0xffffffffu, cnt, 16);
    int maxcnt = cnt > ocnt ? cnt : ocnt;

    float acc = 0.f;
    int   s_cur = 0;
    float dv_cur = 0.f;
    if (0 < cnt) {
        s_cur = __ldg(&g_csr[beg]);
        dv_cur = __ldg(&g_dinv[s_cur]);
    }

#pragma unroll 2
    for (int k = 0; k < maxcnt; ++k) {
        int   s_next = s_cur;
        float dv_next = dv_cur;
        if (k + 1 < cnt) {
            s_next = __ldg(&g_csr[beg + k + 1]);
            dv_next = __ldg(&g_dinv[s_next]);
        }
        if (k < cnt) {
            float hv = __half2float(g_h16[(size_t)s_cur * NCLS + lane]);
            acc = fmaf(hv, dv_cur, acc);
        }
        s_cur = s_next;
        dv_cur = dv_next;
    }

    float di = rsqrtf(1.0f + (float)cnt);
    float hv = __half2float(g_h16[(size_t)node * NCLS + lane]);
    acc = fmaf(hv, di, acc) * di + __ldg(&b[lane]);
    if (RELU) acc = fmaxf(acc, 0.f);
    out[(size_t)node * NCLS + lane] = acc;
}

// ---------------------------------------------------------------------------
// Launch: CSR build (memset + histfill + dinv) || layer-1 GEMM; then layers.
// ---------------------------------------------------------------------------
extern "C" void kernel_launch(void* const* d_in, const int* in_sizes, int n_in,
                              void* d_out, int out_size) {
    const float* x  = (const float*)d_in[0];
    const int*   ei = (const int*)  d_in[1];
    const float* W1 = (const float*)d_in[2];
    const float* b1 = (const float*)d_in[3];
    const float* Wh = (const float*)d_in[4];
    const float* bh = (const float*)d_in[5];
    const float* W2 = (const float*)d_in[6];
    const float* b2 = (const float*)d_in[7];

    float* logits = (float*)d_out;                       // [N, 16]
    float* latent = (float*)d_out + (size_t)NN * NCLS;   // [N, 64]

    float* x1;
    int* cntp;
    cudaGetSymbolAddress((void**)&x1, g_x1);
    cudaGetSymbolAddress((void**)&cntp, g_cnt);

    const int T = 256;
    const int GB = cdiv(NN, 16);   // 2 nodes/warp, 8 warps/block

    // ---- fork: layer-1 GEMM on side stream ----
    cudaEventRecord(g_hx.e_fork, 0);
    cudaStreamWaitEvent(g_hx.s1, g_hx.e_fork, 0);
    k_gemm<FIN, HID><<<cdiv(NN, 128), 128, 0, g_hx.s1>>>(x, W1);
    cudaEventRecord(g_hx.e_join, g_hx.s1);

    // ---- CSR build on default stream (concurrent with GEMM1) ----
    cudaMemsetAsync(cntp, 0, NN * sizeof(int), 0);
    k_histfill<<<cdiv(EE / 4, T), T>>>(ei);
    k_dinv<<<cdiv(NN, T), T>>>();

    // ---- join ----
    cudaStreamWaitEvent(0, g_hx.e_join, 0);

    // layer 1: 128 -> 64, relu
    k_gather64<true><<<GB, T>>>(b1, x1);

    // layer 2: 64 -> 64, relu -> latent
    k_gemm<HID, HID><<<cdiv(NN, 128), 128>>>(x1, Wh);
    k_gather64<true><<<GB, T>>>(bh, latent);

    // layer 3: 64 -> 16, logits
    k_gemm<HID, NCLS><<<cdiv(NN, 128), 128>>>(latent, W2);
    k_gather16<false><<<GB, T>>>(b2, logits);
}

// round 15
// speedup vs baseline: 1.1139x; 1.0666x over previous
#include <cuda_runtime.h>
#include <cuda_fp16.h>
#include <cstdint>

#define NN 100000
#define EE 1600000
#define FIN 128
#define HID 64
#define NCLS 16

#define DSTRIDE 64          // fixed CSR row stride (max degree ~45 << 64)

// ---- scratch (__device__ globals: allocation-free rule) ----
__device__ __align__(16) int    g_cnt[NN];                    // degree (atomic cursor)
__device__ __align__(16) float  g_dinv[NN];                   // rsqrt(1+deg)
__device__ __align__(16) int    g_csr[(size_t)NN * DSTRIDE];  // src only (4B/edge)
__device__ __align__(16) __half g_h16[(size_t)NN * HID];      // fp16 GEMM output
__device__ __align__(16) float  g_x1[(size_t)NN * HID];       // layer-1 output (fp32)

static inline int cdiv(long long a, int b) { return (int)((a + b - 1) / b); }

// ---- side stream + events for capture fork/join (static init, no dev mem) ----
struct HxAsync {
    cudaStream_t s1;
    cudaEvent_t e_fork, e_join;
    HxAsync() {
        cudaStreamCreateWithFlags(&s1, cudaStreamNonBlocking);
        cudaEventCreateWithFlags(&e_fork, cudaEventDisableTiming);
        cudaEventCreateWithFlags(&e_join, cudaEventDisableTiming);
    }
};
static HxAsync g_hx;

// ---------------------------------------------------------------------------
// CSR build: ONE pass, ONE atomic per edge. cnt[d] is hist AND slot cursor.
// ---------------------------------------------------------------------------
__global__ void k_histfill(const int* __restrict__ ei) {
    int t = blockIdx.x * blockDim.x + threadIdx.x;
    if (t >= EE / 4) return;
    int4 s4 = *reinterpret_cast<const int4*>(ei + 4 * t);
    int4 d4 = *reinterpret_cast<const int4*>(ei + EE + 4 * t);
    int slot;
    slot = atomicAdd(&g_cnt[d4.x], 1); if (slot > DSTRIDE - 1) slot = DSTRIDE - 1;
    g_csr[(size_t)d4.x * DSTRIDE + slot] = s4.x;
    slot = atomicAdd(&g_cnt[d4.y], 1); if (slot > DSTRIDE - 1) slot = DSTRIDE - 1;
    g_csr[(size_t)d4.y * DSTRIDE + slot] = s4.y;
    slot = atomicAdd(&g_cnt[d4.z], 1); if (slot > DSTRIDE - 1) slot = DSTRIDE - 1;
    g_csr[(size_t)d4.z * DSTRIDE + slot] = s4.z;
    slot = atomicAdd(&g_cnt[d4.w], 1); if (slot > DSTRIDE - 1) slot = DSTRIDE - 1;
    g_csr[(size_t)d4.w * DSTRIDE + slot] = s4.w;
}

__global__ void k_dinv() {
    int i = blockIdx.x * blockDim.x + threadIdx.x;
    if (i < NN) g_dinv[i] = rsqrtf(1.0f + (float)g_cnt[i]);
}

// ---------------------------------------------------------------------------
// GEMM: g_h16 = fp16(X @ W [* dinv(node) if SCALE]). One thread per node.
// SCALE pre-multiplies the row by dinv so downstream gathers need no weights.
// ---------------------------------------------------------------------------
template <int K, int O, bool SCALE>
__global__ void k_gemm(const float* __restrict__ X, const float* __restrict__ W) {
    __shared__ __align__(16) float Ws[K * O];
    for (int i = threadIdx.x; i < K * O; i += blockDim.x) Ws[i] = W[i];
    __syncthreads();

    int node = blockIdx.x * blockDim.x + threadIdx.x;
    if (node >= NN) return;

    float4 acc[O / 4];
#pragma unroll
    for (int o = 0; o < O / 4; ++o) acc[o] = make_float4(0.f, 0.f, 0.f, 0.f);

    const float4* xr = reinterpret_cast<const float4*>(X + (size_t)node * K);
    for (int k4 = 0; k4 < K / 4; ++k4) {
        float4 xv = xr[k4];
        float xk[4] = {xv.x, xv.y, xv.z, xv.w};
#pragma unroll
        for (int kk = 0; kk < 4; ++kk) {
            const float4* wr = reinterpret_cast<const float4*>(&Ws[(k4 * 4 + kk) * O]);
#pragma unroll
            for (int o = 0; o < O / 4; ++o) {
                float4 w = wr[o];
                acc[o].x = fmaf(xk[kk], w.x, acc[o].x);
                acc[o].y = fmaf(xk[kk], w.y, acc[o].y);
                acc[o].z = fmaf(xk[kk], w.z, acc[o].z);
                acc[o].w = fmaf(xk[kk], w.w, acc[o].w);
            }
        }
    }

    float sc = 1.0f;
    if (SCALE) sc = rsqrtf(1.0f + (float)__ldg(&g_cnt[node]));

    __align__(16) __half2 hbuf[O / 2];
#pragma unroll
    for (int o = 0; o < O / 4; ++o) {
        hbuf[2 * o]     = __floats2half2_rn(acc[o].x * sc, acc[o].y * sc);
        hbuf[2 * o + 1] = __floats2half2_rn(acc[o].z * sc, acc[o].w * sc);
    }
    uint4* dst = reinterpret_cast<uint4*>(&g_h16[(size_t)node * O]);
    const uint4* srcb = reinterpret_cast<const uint4*>(hbuf);
#pragma unroll
    for (int i = 0; i < (O * 2) / 16; ++i) dst[i] = srcb[i];
}

// ---------------------------------------------------------------------------
// Gather (O=64): 2 nodes/warp, 16 lanes/node; joint max-deg loop, 2 edges per
// iteration via paired int2 CSR load. Loads unpredicated (slots always valid);
// tail contributions masked by w=0. WEIGHTED: per-edge w = dinv[src] (layer 1,
// h unscaled). !WEIGHTED: h pre-scaled by dinv (layers 2); w is 1/0 mask.
//   out = (acc + hown[*di if WEIGHTED]) * di + b, optional relu.
// ---------------------------------------------------------------------------
template <bool WEIGHTED, bool RELU>
__global__ void __launch_bounds__(256, 8)
k_gather64(const float* __restrict__ b, float* __restrict__ out) {
    int warp = blockIdx.x * (blockDim.x >> 5) + (threadIdx.x >> 5);
    int half = (threadIdx.x >> 4) & 1;
    int node = warp * 2 + half;          // NN even; grid sized exactly
    int lane = threadIdx.x & 15;

    int cnt = __ldg(&g_cnt[node]);
    int ocnt = __shfl_xor_sync(0xffffffffu, cnt, 16);
    int maxcnt = cnt > ocnt ? cnt : ocnt;

    const int2* crow = reinterpret_cast<const int2*>(g_csr + (size_t)node * DSTRIDE);
    const __half* hlane = g_h16 + 4 * lane;

    float4 a0 = make_float4(0.f, 0.f, 0.f, 0.f);
    float4 a1 = a0;

    for (int k = 0; k < maxcnt; k += 2) {
        int2 c = __ldg(&crow[k >> 1]);
        float w0, w1;
        if (WEIGHTED) {
            w0 = (k     < cnt) ? __ldg(&g_dinv[c.x]) : 0.f;
            w1 = (k + 1 < cnt) ? __ldg(&g_dinv[c.y]) : 0.f;
        } else {
            w0 = (k     < cnt) ? 1.f : 0.f;
            w1 = (k + 1 < cnt) ? 1.f : 0.f;
        }
        uint2 u0 = *reinterpret_cast<const uint2*>(hlane + (size_t)c.x * HID);
        uint2 u1 = *reinterpret_cast<const uint2*>(hlane + (size_t)c.y * HID);
        float2 p0 = __half22float2(*reinterpret_cast<__half2*>(&u0.x));
        float2 q0 = __half22float2(*reinterpret_cast<__half2*>(&u0.y));
        float2 p1 = __half22float2(*reinterpret_cast<__half2*>(&u1.x));
        float2 q1 = __half22float2(*reinterpret_cast<__half2*>(&u1.y));
        a0.x = fmaf(p0.x, w0, a0.x); a0.y = fmaf(p0.y, w0, a0.y);
        a0.z = fmaf(q0.x, w0, a0.z); a0.w = fmaf(q0.y, w0, a0.w);
        a1.x = fmaf(p1.x, w1, a1.x); a1.y = fmaf(p1.y, w1, a1.y);
        a1.z = fmaf(q1.x, w1, a1.z); a1.w = fmaf(q1.y, w1, a1.w);
    }

    float4 acc;
    acc.x = a0.x + a1.x;
    acc.y = a0.y + a1.y;
    acc.z = a0.z + a1.z;
    acc.w = a0.w + a1.w;

    float di = rsqrtf(1.0f + (float)cnt);
    uint2 u = *reinterpret_cast<const uint2*>(hlane + (size_t)node * HID);
    float2 f01 = __half22float2(*reinterpret_cast<__half2*>(&u.x));
    float2 f23 = __half22float2(*reinterpret_cast<__half2*>(&u.y));
    float4 bv = *reinterpret_cast<const float4*>(&b[4 * lane]);
    float sf = WEIGHTED ? di : 1.0f;     // self term: h*di (unscaled) or h' (scaled)
    acc.x = fmaf(f01.x, sf, acc.x) * di + bv.x;
    acc.y = fmaf(f01.y, sf, acc.y) * di + bv.y;
    acc.z = fmaf(f23.x, sf, acc.z) * di + bv.z;
    acc.w = fmaf(f23.y, sf, acc.w) * di + bv.w;
    if (RELU) {
        acc.x = fmaxf(acc.x, 0.f);
        acc.y = fmaxf(acc.y, 0.f);
        acc.z = fmaxf(acc.z, 0.f);
        acc.w = fmaxf(acc.w, 0.f);
    }
    *reinterpret_cast<float4*>(&out[(size_t)node * HID + 4 * lane]) = acc;
}

// ---------------------------------------------------------------------------
// Gather (O=16): 2 nodes/warp, 16 lanes x 1 half; pre-scaled h (no weights),
// 2 edges per iteration via int2 CSR load.
// ---------------------------------------------------------------------------
__global__ void __launch_bounds__(256, 8)
k_gather16(const float* __restrict__ b, float* __restrict__ out) {
    int warp = blockIdx.x * (blockDim.x >> 5) + (threadIdx.x >> 5);
    int half = (threadIdx.x >> 4) & 1;
    int node = warp * 2 + half;
    int lane = threadIdx.x & 15;

    int cnt = __ldg(&g_cnt[node]);
    int ocnt = __shfl_xor_sync(0xffffffffu, cnt, 16);
    int maxcnt = cnt > ocnt ? cnt : ocnt;

    const int2* crow = reinterpret_cast<const int2*>(g_csr + (size_t)node * DSTRIDE);
    const __half* hlane = g_h16 + lane;

    float a0 = 0.f, a1 = 0.f;
    for (int k = 0; k < maxcnt; k += 2) {
        int2 c = __ldg(&crow[k >> 1]);
        float w0 = (k     < cnt) ? 1.f : 0.f;
        float w1 = (k + 1 < cnt) ? 1.f : 0.f;
        float h0 = __half2float(hlane[(size_t)c.x * NCLS]);
        float h1 = __half2float(hlane[(size_t)c.y * NCLS]);
        a0 = fmaf(h0, w0, a0);
        a1 = fmaf(h1, w1, a1);
    }
    float acc = a0 + a1;

    float di = rsqrtf(1.0f + (float)cnt);
    float hv = __half2float(hlane[(size_t)node * NCLS]);
    acc = (acc + hv) * di + __ldg(&b[lane]);
    out[(size_t)node * NCLS + lane] = acc;
}

// ---------------------------------------------------------------------------
// Launch: CSR build (memset + histfill + dinv) || layer-1 GEMM; then layers.
// ---------------------------------------------------------------------------
extern "C" void kernel_launch(void* const* d_in, const int* in_sizes, int n_in,
                              void* d_out, int out_size) {
    const float* x  = (const float*)d_in[0];
    const int*   ei = (const int*)  d_in[1];
    const float* W1 = (const float*)d_in[2];
    const float* b1 = (const float*)d_in[3];
    const float* Wh = (const float*)d_in[4];
    const float* bh = (const float*)d_in[5];
    const float* W2 = (const float*)d_in[6];
    const float* b2 = (const float*)d_in[7];

    float* logits = (float*)d_out;                       // [N, 16]
    float* latent = (float*)d_out + (size_t)NN * NCLS;   // [N, 64]

    float* x1;
    int* cntp;
    cudaGetSymbolAddress((void**)&x1, g_x1);
    cudaGetSymbolAddress((void**)&cntp, g_cnt);

    const int T = 256;
    const int GB = cdiv(NN, 16);   // 2 nodes/warp, 8 warps/block

    // ---- fork: layer-1 GEMM on side stream (unscaled output) ----
    cudaEventRecord(g_hx.e_fork, 0);
    cudaStreamWaitEvent(g_hx.s1, g_hx.e_fork, 0);
    k_gemm<FIN, HID, false><<<cdiv(NN, 128), 128, 0, g_hx.s1>>>(x, W1);
    cudaEventRecord(g_hx.e_join, g_hx.s1);

    // ---- CSR build on default stream (concurrent with GEMM1) ----
    cudaMemsetAsync(cntp, 0, NN * sizeof(int), 0);
    k_histfill<<<cdiv(EE / 4, T), T>>>(ei);
    k_dinv<<<cdiv(NN, T), T>>>();

    // ---- join ----
    cudaStreamWaitEvent(0, g_hx.e_join, 0);

    // layer 1: 128 -> 64, relu (weighted gather: h unscaled)
    k_gather64<true, true><<<GB, T>>>(b1, x1);

    // layer 2: 64 -> 64, relu -> latent (GEMM pre-scales by dinv)
    k_gemm<HID, HID, true><<<cdiv(NN, 128), 128>>>(x1, Wh);
    k_gather64<false, true><<<GB, T>>>(bh, latent);

    // layer 3: 64 -> 16, logits (GEMM pre-scales by dinv)
    k_gemm<HID, NCLS, true><<<cdiv(NN, 128), 128>>>(latent, W2);
    k_gather16<<<GB, T>>>(b2, logits);
}

// round 16
// speedup vs baseline: 1.1829x; 1.0619x over previous
#include <cuda_runtime.h>
#include <cuda_fp16.h>
#include <cstdint>

#define NN 100000
#define EE 1600000
#define FIN 128
#define HID 64
#define NCLS 16

#define DSTRIDE 64          // fixed CSR row stride (max degree ~45 << 64)

// ---- scratch (__device__ globals: allocation-free rule) ----
__device__ __align__(16) int    g_cnt[NN];                    // degree (atomic cursor)
__device__ __align__(16) float  g_dinv[NN];                   // rsqrt(1+deg)
__device__ __align__(16) int    g_csr[(size_t)NN * DSTRIDE];  // src only (4B/edge)
__device__ __align__(16) __half g_h16[(size_t)NN * HID];      // fp16 GEMM output (pre-scaled)
__device__ __align__(16) float  g_x1[(size_t)NN * HID];       // layer-1 output (fp32)

static inline int cdiv(long long a, int b) { return (int)((a + b - 1) / b); }

// ---- side stream + events for capture fork/join (static init, no dev mem) ----
struct HxAsync {
    cudaStream_t s1;
    cudaEvent_t e_fork, e_dinv, e_join;
    HxAsync() {
        cudaStreamCreateWithFlags(&s1, cudaStreamNonBlocking);
        cudaEventCreateWithFlags(&e_fork, cudaEventDisableTiming);
        cudaEventCreateWithFlags(&e_dinv, cudaEventDisableTiming);
        cudaEventCreateWithFlags(&e_join, cudaEventDisableTiming);
    }
};
static HxAsync g_hx;

// ---------------------------------------------------------------------------
// CSR build: ONE pass, ONE atomic per edge. cnt[d] is hist AND slot cursor.
// ---------------------------------------------------------------------------
__global__ void k_histfill(const int* __restrict__ ei) {
    int t = blockIdx.x * blockDim.x + threadIdx.x;
    if (t >= EE / 4) return;
    int4 s4 = *reinterpret_cast<const int4*>(ei + 4 * t);
    int4 d4 = *reinterpret_cast<const int4*>(ei + EE + 4 * t);
    int slot;
    slot = atomicAdd(&g_cnt[d4.x], 1); if (slot > DSTRIDE - 1) slot = DSTRIDE - 1;
    g_csr[(size_t)d4.x * DSTRIDE + slot] = s4.x;
    slot = atomicAdd(&g_cnt[d4.y], 1); if (slot > DSTRIDE - 1) slot = DSTRIDE - 1;
    g_csr[(size_t)d4.y * DSTRIDE + slot] = s4.y;
    slot = atomicAdd(&g_cnt[d4.z], 1); if (slot > DSTRIDE - 1) slot = DSTRIDE - 1;
    g_csr[(size_t)d4.z * DSTRIDE + slot] = s4.z;
    slot = atomicAdd(&g_cnt[d4.w], 1); if (slot > DSTRIDE - 1) slot = DSTRIDE - 1;
    g_csr[(size_t)d4.w * DSTRIDE + slot] = s4.w;
}

__global__ void k_dinv() {
    int i = blockIdx.x * blockDim.x + threadIdx.x;
    if (i < NN) g_dinv[i] = rsqrtf(1.0f + (float)g_cnt[i]);
}

// ---------------------------------------------------------------------------
// Scale h16 rows in place by dinv[node]: one uint4 (8 halves) per thread.
// Runs on side stream after GEMM1 and k_dinv both complete.
// ---------------------------------------------------------------------------
__global__ void k_scale() {
    int t = blockIdx.x * blockDim.x + threadIdx.x;
    if (t >= NN * HID / 8) return;
    int node = t >> 3;                 // 8 uint4 per 64-half row
    float sc = g_dinv[node];
    uint4 v = *(reinterpret_cast<uint4*>(g_h16) + t);
    uint32_t w[4] = {v.x, v.y, v.z, v.w};
#pragma unroll
    for (int i = 0; i < 4; ++i) {
        float2 f = __half22float2(*reinterpret_cast<__half2*>(&w[i]));
        __half2 r = __floats2half2_rn(f.x * sc, f.y * sc);
        w[i] = *reinterpret_cast<uint32_t*>(&r);
    }
    *(reinterpret_cast<uint4*>(g_h16) + t) = make_uint4(w[0], w[1], w[2], w[3]);
}

// ---------------------------------------------------------------------------
// GEMM: g_h16 = fp16(X @ W [* dinv(node) if SCALE]). One thread per node.
// SCALE pre-multiplies the row by dinv so downstream gathers need no weights.
// ---------------------------------------------------------------------------
template <int K, int O, bool SCALE>
__global__ void k_gemm(const float* __restrict__ X, const float* __restrict__ W) {
    __shared__ __align__(16) float Ws[K * O];
    for (int i = threadIdx.x; i < K * O; i += blockDim.x) Ws[i] = W[i];
    __syncthreads();

    int node = blockIdx.x * blockDim.x + threadIdx.x;
    if (node >= NN) return;

    float4 acc[O / 4];
#pragma unroll
    for (int o = 0; o < O / 4; ++o) acc[o] = make_float4(0.f, 0.f, 0.f, 0.f);

    const float4* xr = reinterpret_cast<const float4*>(X + (size_t)node * K);
    for (int k4 = 0; k4 < K / 4; ++k4) {
        float4 xv = xr[k4];
        float xk[4] = {xv.x, xv.y, xv.z, xv.w};
#pragma unroll
        for (int kk = 0; kk < 4; ++kk) {
            const float4* wr = reinterpret_cast<const float4*>(&Ws[(k4 * 4 + kk) * O]);
#pragma unroll
            for (int o = 0; o < O / 4; ++o) {
                float4 w = wr[o];
                acc[o].x = fmaf(xk[kk], w.x, acc[o].x);
                acc[o].y = fmaf(xk[kk], w.y, acc[o].y);
                acc[o].z = fmaf(xk[kk], w.z, acc[o].z);
                acc[o].w = fmaf(xk[kk], w.w, acc[o].w);
            }
        }
    }

    float sc = 1.0f;
    if (SCALE) sc = rsqrtf(1.0f + (float)__ldg(&g_cnt[node]));

    __align__(16) __half2 hbuf[O / 2];
#pragma unroll
    for (int o = 0; o < O / 4; ++o) {
        hbuf[2 * o]     = __floats2half2_rn(acc[o].x * sc, acc[o].y * sc);
        hbuf[2 * o + 1] = __floats2half2_rn(acc[o].z * sc, acc[o].w * sc);
    }
    uint4* dst = reinterpret_cast<uint4*>(&g_h16[(size_t)node * O]);
    const uint4* srcb = reinterpret_cast<const uint4*>(hbuf);
#pragma unroll
    for (int i = 0; i < (O * 2) / 16; ++i) dst[i] = srcb[i];
}

// ---------------------------------------------------------------------------
// Gather (O=64): 2 nodes/warp, 16 lanes/node; joint max-deg loop, 2 edges per
// iteration via paired int2 CSR load (unroll 2 -> 4 edges in flight).
// h pre-scaled by dinv; tail contributions masked by w=0.
//   out = (acc + h'own) * di + b, optional relu.
// ---------------------------------------------------------------------------
template <bool RELU>
__global__ void __launch_bounds__(256, 8)
k_gather64(const float* __restrict__ b, float* __restrict__ out) {
    int warp = blockIdx.x * (blockDim.x >> 5) + (threadIdx.x >> 5);
    int half = (threadIdx.x >> 4) & 1;
    int node = warp * 2 + half;          // NN even; grid sized exactly
    int lane = threadIdx.x & 15;

    int cnt = __ldg(&g_cnt[node]);
    int ocnt = __shfl_xor_sync(0xffffffffu, cnt, 16);
    int maxcnt = cnt > ocnt ? cnt : ocnt;

    const int2* crow = reinterpret_cast<const int2*>(g_csr + (size_t)node * DSTRIDE);
    const __half* hlane = g_h16 + 4 * lane;

    float4 a0 = make_float4(0.f, 0.f, 0.f, 0.f);
    float4 a1 = a0;

#pragma unroll 2
    for (int k = 0; k < maxcnt; k += 2) {
        int2 c = __ldg(&crow[k >> 1]);
        float w0 = (k     < cnt) ? 1.f : 0.f;
        float w1 = (k + 1 < cnt) ? 1.f : 0.f;
        uint2 u0 = *reinterpret_cast<const uint2*>(hlane + (size_t)c.x * HID);
        uint2 u1 = *reinterpret_cast<const uint2*>(hlane + (size_t)c.y * HID);
        float2 p0 = __half22float2(*reinterpret_cast<__half2*>(&u0.x));
        float2 q0 = __half22float2(*reinterpret_cast<__half2*>(&u0.y));
        float2 p1 = __half22float2(*reinterpret_cast<__half2*>(&u1.x));
        float2 q1 = __half22float2(*reinterpret_cast<__half2*>(&u1.y));
        a0.x = fmaf(p0.x, w0, a0.x); a0.y = fmaf(p0.y, w0, a0.y);
        a0.z = fmaf(q0.x, w0, a0.z); a0.w = fmaf(q0.y, w0, a0.w);
        a1.x = fmaf(p1.x, w1, a1.x); a1.y = fmaf(p1.y, w1, a1.y);
        a1.z = fmaf(q1.x, w1, a1.z); a1.w = fmaf(q1.y, w1, a1.w);
    }

    float4 acc;
    acc.x = a0.x + a1.x;
    acc.y = a0.y + a1.y;
    acc.z = a0.z + a1.z;
    acc.w = a0.w + a1.w;

    float di = rsqrtf(1.0f + (float)cnt);
    uint2 u = *reinterpret_cast<const uint2*>(hlane + (size_t)node * HID);
    float2 f01 = __half22float2(*reinterpret_cast<__half2*>(&u.x));
    float2 f23 = __half22float2(*reinterpret_cast<__half2*>(&u.y));
    float4 bv = *reinterpret_cast<const float4*>(&b[4 * lane]);
    acc.x = (acc.x + f01.x) * di + bv.x;
    acc.y = (acc.y + f01.y) * di + bv.y;
    acc.z = (acc.z + f23.x) * di + bv.z;
    acc.w = (acc.w + f23.y) * di + bv.w;
    if (RELU) {
        acc.x = fmaxf(acc.x, 0.f);
        acc.y = fmaxf(acc.y, 0.f);
        acc.z = fmaxf(acc.z, 0.f);
        acc.w = fmaxf(acc.w, 0.f);
    }
    *reinterpret_cast<float4*>(&out[(size_t)node * HID + 4 * lane]) = acc;
}

// ---------------------------------------------------------------------------
// Gather (O=16): 2 nodes/warp, 16 lanes x 1 half; pre-scaled h,
// 2 edges per iteration via int2 CSR load (unroll 2).
// ---------------------------------------------------------------------------
__global__ void __launch_bounds__(256, 8)
k_gather16(const float* __restrict__ b, float* __restrict__ out) {
    int warp = blockIdx.x * (blockDim.x >> 5) + (threadIdx.x >> 5);
    int half = (threadIdx.x >> 4) & 1;
    int node = warp * 2 + half;
    int lane = threadIdx.x & 15;

    int cnt = __ldg(&g_cnt[node]);
    int ocnt = __shfl_xor_sync(0xffffffffu, cnt, 16);
    int maxcnt = cnt > ocnt ? cnt : ocnt;

    const int2* crow = reinterpret_cast<const int2*>(g_csr + (size_t)node * DSTRIDE);
    const __half* hlane = g_h16 + lane;

    float a0 = 0.f, a1 = 0.f;
#pragma unroll 2
    for (int k = 0; k < maxcnt; k += 2) {
        int2 c = __ldg(&crow[k >> 1]);
        float w0 = (k     < cnt) ? 1.f : 0.f;
        float w1 = (k + 1 < cnt) ? 1.f : 0.f;
        float h0 = __half2float(hlane[(size_t)c.x * NCLS]);
        float h1 = __half2float(hlane[(size_t)c.y * NCLS]);
        a0 = fmaf(h0, w0, a0);
        a1 = fmaf(h1, w1, a1);
    }
    float acc = a0 + a1;

    float di = rsqrtf(1.0f + (float)cnt);
    float hv = __half2float(hlane[(size_t)node * NCLS]);
    acc = (acc + hv) * di + __ldg(&b[lane]);
    out[(size_t)node * NCLS + lane] = acc;
}

// ---------------------------------------------------------------------------
// Launch: default: memset+histfill+dinv || side: GEMM1, then scale (after
// dinv). Join; then unweighted gather/GEMM chain.
// ---------------------------------------------------------------------------
extern "C" void kernel_launch(void* const* d_in, const int* in_sizes, int n_in,
                              void* d_out, int out_size) {
    const float* x  = (const float*)d_in[0];
    const int*   ei = (const int*)  d_in[1];
    const float* W1 = (const float*)d_in[2];
    const float* b1 = (const float*)d_in[3];
    const float* Wh = (const float*)d_in[4];
    const float* bh = (const float*)d_in[5];
    const float* W2 = (const float*)d_in[6];
    const float* b2 = (const float*)d_in[7];

    float* logits = (float*)d_out;                       // [N, 16]
    float* latent = (float*)d_out + (size_t)NN * NCLS;   // [N, 64]

    float* x1;
    int* cntp;
    cudaGetSymbolAddress((void**)&x1, g_x1);
    cudaGetSymbolAddress((void**)&cntp, g_cnt);

    const int T = 256;
    const int GB = cdiv(NN, 16);   // 2 nodes/warp, 8 warps/block

    // ---- fork: layer-1 GEMM (unscaled) on side stream ----
    cudaEventRecord(g_hx.e_fork, 0);
    cudaStreamWaitEvent(g_hx.s1, g_hx.e_fork, 0);
    k_gemm<FIN, HID, false><<<cdiv(NN, 128), 128, 0, g_hx.s1>>>(x, W1);

    // ---- CSR build on default stream (concurrent with GEMM1) ----
    cudaMemsetAsync(cntp, 0, NN * sizeof(int), 0);
    k_histfill<<<cdiv(EE / 4, T), T>>>(ei);
    k_dinv<<<cdiv(NN, T), T>>>();
    cudaEventRecord(g_hx.e_dinv, 0);

    // ---- side: scale h16 by dinv once both GEMM1 and dinv are done ----
    cudaStreamWaitEvent(g_hx.s1, g_hx.e_dinv, 0);
    k_scale<<<cdiv((long long)NN * HID / 8, T), T, 0, g_hx.s1>>>();
    cudaEventRecord(g_hx.e_join, g_hx.s1);

    // ---- join ----
    cudaStreamWaitEvent(0, g_hx.e_join, 0);

    // layer 1: 128 -> 64, relu (unweighted gather on pre-scaled h)
    k_gather64<true><<<GB, T>>>(b1, x1);

    // layer 2: 64 -> 64, relu -> latent (GEMM pre-scales by dinv)
    k_gemm<HID, HID, true><<<cdiv(NN, 128), 128>>>(x1, Wh);
    k_gather64<true><<<GB, T>>>(bh, latent);

    // layer 3: 64 -> 16, logits (GEMM pre-scales by dinv)
    k_gemm<HID, NCLS, true><<<cdiv(NN, 128), 128>>>(latent, W2);
    k_gather16<<<GB, T>>>(b2, logits);
}